// round 15
// baseline (speedup 1.0000x reference)
#include <cuda_runtime.h>
#include <cuda_fp16.h>

#define NN 50000
#define NE 800000
#define HCD 64
#define NTILES 49   // ceil(50000/1024)

// ---------------- scratch (static device globals; allocation-free) ----------
__device__ __align__(16) __half2 g_xs[NN * 32];     // xs of current layer (fp16!)
__device__ __align__(16) float g_h1[NN * HCD];      // relu(layer1 out), fp32
__device__ __align__(16) float g_acc[NN * HCD];     // layer2 out (pre-pool)
__device__ __align__(16) float g_asrc[NN * 4];      // per-node a_src (4 heads, fp32)
__device__ __align__(16) float g_adst[NN * 4];      // per-node a_dst (fp32)
__device__ __align__(16) float g_ce[8];             // [0..3] layer1, [4..7] layer2
// CSR build
__device__ int g_deg[NN];
__device__ int g_start[NN + 1];
__device__ int g_cursor[NN];
__device__ int g_bsum[NTILES];
__device__ __align__(16) int2 g_edge[NE];           // {src, ea bits} in CSR order

// ---------------- helpers ----------------------------------------------------
__device__ __forceinline__ float red16(float v) {
    v += __shfl_xor_sync(0xffffffffu, v, 8);
    v += __shfl_xor_sync(0xffffffffu, v, 4);
    v += __shfl_xor_sync(0xffffffffu, v, 2);
    v += __shfl_xor_sync(0xffffffffu, v, 1);
    return v;
}

// ---------------- hist (8 edges/thread) + fused ce constants -----------------
__global__ void k_hist(const int* __restrict__ ei,
                       const float* __restrict__ We1, const float* __restrict__ ae1,
                       const float* __restrict__ We2, const float* __restrict__ ae2) {
    if (blockIdx.x == 0 && threadIdx.x < 128) {
        int t = threadIdx.x;
        int layer = t >> 6;
        int c = t & 63;
        const float* We = layer ? We2 : We1;
        const float* ae = layer ? ae2 : ae1;
        float v = red16(We[c] * ae[c]);
        if ((c & 15) == 0) g_ce[layer * 4 + (c >> 4)] = v;
    }
    int t = blockIdx.x * blockDim.x + threadIdx.x;
    int e = t * 8;
    if (e >= NE) return;
    int4 d0 = *(const int4*)&ei[NE + e];
    int4 d1 = *(const int4*)&ei[NE + e + 4];
    atomicAdd(&g_deg[d0.x], 1); atomicAdd(&g_deg[d0.y], 1);
    atomicAdd(&g_deg[d0.z], 1); atomicAdd(&g_deg[d0.w], 1);
    atomicAdd(&g_deg[d1.x], 1); atomicAdd(&g_deg[d1.y], 1);
    atomicAdd(&g_deg[d1.z], 1); atomicAdd(&g_deg[d1.w], 1);
}

// ---------------- scan -------------------------------------------------------
__global__ void k_scanA() {           // per-tile reduction
    __shared__ int wsum[32];
    int b = blockIdx.x, tid = threadIdx.x, lane = tid & 31, w = tid >> 5;
    int i = b * 1024 + tid;
    int v = (i < NN) ? g_deg[i] : 0;
#pragma unroll
    for (int d = 16; d; d >>= 1) v += __shfl_xor_sync(0xffffffffu, v, d);
    if (lane == 0) wsum[w] = v;
    __syncthreads();
    if (w == 0) {
        int t = wsum[lane];
#pragma unroll
        for (int d = 16; d; d >>= 1) t += __shfl_xor_sync(0xffffffffu, t, d);
        if (lane == 0) g_bsum[b] = t;
    }
}

// per-tile scan + (redundant) scan of tile sums for the global offset.
// Cross-warp handoff uses BLOCK-level barriers.
__global__ void k_scanC() {
    __shared__ int wsum[32];
    __shared__ int sboff;
    __shared__ int ws2[2];
    int b = blockIdx.x, tid = threadIdx.x, lane = tid & 31, w = tid >> 5;

    int v2 = 0, x2 = 0;
    if (tid < 64) {
        v2 = (tid < NTILES) ? g_bsum[tid] : 0;
        x2 = v2;
#pragma unroll
        for (int d = 1; d < 32; d <<= 1) {
            int y = __shfl_up_sync(0xffffffffu, x2, d);
            if (lane >= d) x2 += y;
        }
        if (lane == 31) ws2[w] = x2;
    }
    __syncthreads();                       // publish ws2[0] to warp 1
    if (tid >= 32 && tid < 64) x2 += ws2[0];
    if (tid == b) sboff = x2 - v2;         // exclusive offset of this tile
    if (b == 0 && tid == NTILES - 1) g_start[NN] = x2;
    __syncthreads();                       // publish sboff

    int i = b * 1024 + tid;
    int v = (i < NN) ? g_deg[i] : 0;
    int x = v;
#pragma unroll
    for (int d = 1; d < 32; d <<= 1) {
        int y = __shfl_up_sync(0xffffffffu, x, d);
        if (lane >= d) x += y;
    }
    if (lane == 31) wsum[w] = x;
    __syncthreads();
    if (w == 0) {
        int t = wsum[lane];
#pragma unroll
        for (int d = 1; d < 32; d <<= 1) {
            int y = __shfl_up_sync(0xffffffffu, t, d);
            if (lane >= d) t += y;
        }
        wsum[lane] = t;
    }
    __syncthreads();
    int excl = sboff + (w ? wsum[w - 1] : 0) + x - v;
    if (i < NN) { g_start[i] = excl; g_cursor[i] = excl; }
}

// 8 edges per thread, vector loads for MLP.
__global__ void k_scatter(const int* __restrict__ ei, const float* __restrict__ ea) {
    int t = blockIdx.x * blockDim.x + threadIdx.x;
    int e = t * 8;
    if (e >= NE) return;
    int4   s0 = *(const int4*)&ei[e];
    int4   s1 = *(const int4*)&ei[e + 4];
    int4   d0 = *(const int4*)&ei[NE + e];
    int4   d1 = *(const int4*)&ei[NE + e + 4];
    float4 a0 = *(const float4*)&ea[e];
    float4 a1 = *(const float4*)&ea[e + 4];
    int p;
    p = atomicAdd(&g_cursor[d0.x], 1); g_edge[p] = make_int2(s0.x, __float_as_int(a0.x));
    p = atomicAdd(&g_cursor[d0.y], 1); g_edge[p] = make_int2(s0.y, __float_as_int(a0.y));
    p = atomicAdd(&g_cursor[d0.z], 1); g_edge[p] = make_int2(s0.z, __float_as_int(a0.z));
    p = atomicAdd(&g_cursor[d0.w], 1); g_edge[p] = make_int2(s0.w, __float_as_int(a0.w));
    p = atomicAdd(&g_cursor[d1.x], 1); g_edge[p] = make_int2(s1.x, __float_as_int(a1.x));
    p = atomicAdd(&g_cursor[d1.y], 1); g_edge[p] = make_int2(s1.y, __float_as_int(a1.y));
    p = atomicAdd(&g_cursor[d1.z], 1); g_edge[p] = make_int2(s1.z, __float_as_int(a1.z));
    p = atomicAdd(&g_cursor[d1.w], 1); g_edge[p] = make_int2(s1.w, __float_as_int(a1.w));
}

// ---------------- register-blocked linear ------------------------------------
// xs = X @ W  (X:[N,D], W:[D,64]); fused a_src/a_dst head-dot reductions
// (computed in fp32 BEFORE the fp16 conversion of the stored xs).
template<int D>
__global__ void __launch_bounds__(256) k_linear(const float* __restrict__ Xext,
                                                const float* __restrict__ W,
                                                const float* __restrict__ as_,
                                                const float* __restrict__ ad_) {
    __shared__ float Wsh[D * 64];
    __shared__ float Xsh[128 * D];
    const float* X = Xext ? Xext : g_h1;
    int tid = threadIdx.x;
    int cg = tid & 7, ng = tid >> 3;
    int c0 = cg * 8;
    int h = cg >> 1;

    for (int i = tid * 4; i < D * 64; i += 1024)
        *(float4*)&Wsh[i] = *(const float4*)&W[i];

    int n0 = blockIdx.x * 128;
    int cnt = NN - n0; if (cnt > 128) cnt = 128;
    for (int i = tid * 4; i < cnt * D; i += 1024)
        *(float4*)&Xsh[i] = *(const float4*)&X[n0 * D + i];
    __syncthreads();

    float acc[4][8];
#pragma unroll
    for (int i = 0; i < 4; i++)
#pragma unroll
        for (int j = 0; j < 8; j++) acc[i][j] = 0.f;

#pragma unroll 2
    for (int k = 0; k < D; k++) {
        float4 wlo = *(const float4*)&Wsh[k * 64 + c0];
        float4 whi = *(const float4*)&Wsh[k * 64 + c0 + 4];
        float wr[8] = {wlo.x, wlo.y, wlo.z, wlo.w, whi.x, whi.y, whi.z, whi.w};
#pragma unroll
        for (int i = 0; i < 4; i++) {
            float xv = Xsh[(ng * 4 + i) * D + k];
#pragma unroll
            for (int j = 0; j < 8; j++)
                acc[i][j] = fmaf(xv, wr[j], acc[i][j]);
        }
    }

    float asv[8], adv[8];
#pragma unroll
    for (int j = 0; j < 8; j++) { asv[j] = as_[c0 + j]; adv[j] = ad_[c0 + j]; }

#pragma unroll
    for (int i = 0; i < 4; i++) {
        int node = n0 + ng * 4 + i;
        float ps = 0.f, pd = 0.f;
#pragma unroll
        for (int j = 0; j < 8; j++) {
            ps = fmaf(acc[i][j], asv[j], ps);
            pd = fmaf(acc[i][j], adv[j], pd);
        }
        ps += __shfl_xor_sync(0xffffffffu, ps, 1);
        pd += __shfl_xor_sync(0xffffffffu, pd, 1);
        if (node < NN) {
            // pack 8 channels into 4 half2 = one 16B store
            __half2 hx[4];
            hx[0] = __floats2half2_rn(acc[i][0], acc[i][1]);
            hx[1] = __floats2half2_rn(acc[i][2], acc[i][3]);
            hx[2] = __floats2half2_rn(acc[i][4], acc[i][5]);
            hx[3] = __floats2half2_rn(acc[i][6], acc[i][7]);
            *(uint4*)&g_xs[node * 32 + cg * 4] = *(const uint4*)hx;
            if ((cg & 1) == 0) {
                g_asrc[node * 4 + h] = ps;
                g_adst[node * 4 + h] = pd;
            }
        }
    }
}

// ---------------- single-pass fused edge aggregation (one warp per dst) ------
// Unrolled x4: batch-load 4 edge records (2x int4), then 4 asrc + 4 xs gathers
// before any dependent math. xs rows are fp16: lane loads one half2 (4B) at
// g_xs[src*32+lane] -> warp reads one coalesced 128B row per edge.
__global__ void k_edge_fused(int layer, const float* __restrict__ bias,
                             float* __restrict__ out, int relu) {
    int gw = (blockIdx.x * blockDim.x + threadIdx.x) >> 5;
    if (gw >= NN) return;
    int lane = threadIdx.x & 31;
    int c = lane * 2;               // two consecutive channels, same head
    int h = lane >> 3;
    int s0 = g_start[gw], s1 = g_start[gw + 1];

    float adh = g_adst[gw * 4 + h];
    float cfh = g_ce[layer * 4 + h];

    float acc0 = 0.f, acc1 = 0.f, dsum = 0.f;

    int j = s0;
    // align j to even so int4 loads of g_edge are 16B-aligned
    if (j < s1 && (j & 1)) {
        int2 ep = g_edge[j];
        float sh = g_asrc[ep.x * 4 + h];
        float2 xv = __half22float2(g_xs[ep.x * 32 + lane]);
        float t = sh + adh + cfh * __int_as_float(ep.y);
        t = t > 0.f ? t : 0.2f * t;
        float w = __expf(t);
        dsum += w;
        acc0 = fmaf(w, xv.x, acc0);
        acc1 = fmaf(w, xv.y, acc1);
        ++j;
    }
    for (; j + 3 < s1; j += 4) {
        int4 eA = *(const int4*)&g_edge[j];
        int4 eB = *(const int4*)&g_edge[j + 2];
        int n0i = eA.x, n1i = eA.z, n2i = eB.x, n3i = eB.z;
        // issue all gathers up front
        float sh0 = g_asrc[n0i * 4 + h];
        float sh1 = g_asrc[n1i * 4 + h];
        float sh2 = g_asrc[n2i * 4 + h];
        float sh3 = g_asrc[n3i * 4 + h];
        __half2 xh0 = g_xs[n0i * 32 + lane];
        __half2 xh1 = g_xs[n1i * 32 + lane];
        __half2 xh2 = g_xs[n2i * 32 + lane];
        __half2 xh3 = g_xs[n3i * 32 + lane];
        float t0 = sh0 + adh + cfh * __int_as_float(eA.y);
        float t1 = sh1 + adh + cfh * __int_as_float(eA.w);
        float t2 = sh2 + adh + cfh * __int_as_float(eB.y);
        float t3 = sh3 + adh + cfh * __int_as_float(eB.w);
        t0 = t0 > 0.f ? t0 : 0.2f * t0;
        t1 = t1 > 0.f ? t1 : 0.2f * t1;
        t2 = t2 > 0.f ? t2 : 0.2f * t2;
        t3 = t3 > 0.f ? t3 : 0.2f * t3;
        float w0 = __expf(t0), w1 = __expf(t1), w2 = __expf(t2), w3 = __expf(t3);
        dsum += (w0 + w1) + (w2 + w3);
        float2 x0 = __half22float2(xh0);
        float2 x1 = __half22float2(xh1);
        float2 x2 = __half22float2(xh2);
        float2 x3 = __half22float2(xh3);
        acc0 = fmaf(w0, x0.x, acc0); acc1 = fmaf(w0, x0.y, acc1);
        acc0 = fmaf(w1, x1.x, acc0); acc1 = fmaf(w1, x1.y, acc1);
        acc0 = fmaf(w2, x2.x, acc0); acc1 = fmaf(w2, x2.y, acc1);
        acc0 = fmaf(w3, x3.x, acc0); acc1 = fmaf(w3, x3.y, acc1);
    }
    for (; j < s1; ++j) {
        int2 ep = g_edge[j];
        float sh = g_asrc[ep.x * 4 + h];
        float2 xv = __half22float2(g_xs[ep.x * 32 + lane]);
        float t = sh + adh + cfh * __int_as_float(ep.y);
        t = t > 0.f ? t : 0.2f * t;
        float w = __expf(t);
        dsum += w;
        acc0 = fmaf(w, xv.x, acc0);
        acc1 = fmaf(w, xv.y, acc1);
    }

    float rcp = (dsum > 0.f) ? (1.f / dsum) : 0.f;
    float2 bv = *(const float2*)&bias[c];
    float o0 = acc0 * rcp + bv.x;
    float o1 = acc1 * rcp + bv.y;
    if (relu) { o0 = fmaxf(o0, 0.f); o1 = fmaxf(o1, 0.f); }
    float2 ov; ov.x = o0; ov.y = o1;
    *(float2*)&out[gw * HCD + c] = ov;
}

// ---------------- pool (batch is sorted -> segment mean per graph) -----------
__device__ __forceinline__ int lowerb(const int* a, int n, int key) {
    int lo = 0, hi = n;
    while (lo < hi) { int m = (lo + hi) >> 1; if (a[m] < key) lo = m + 1; else hi = m; }
    return lo;
}

__global__ void k_pool(const int* __restrict__ batch, float* __restrict__ out) {
    int g = blockIdx.x;
    int lo = lowerb(batch, NN, g);
    int hi = lowerb(batch, NN, g + 1);
    int tid = threadIdx.x;             // 256
    int c = tid & 63, s = tid >> 6;    // 4 slices
    float acc = 0.f;
    for (int n = lo + s; n < hi; n += 4) acc += g_acc[n * HCD + c];
    __shared__ float sh[256];
    sh[tid] = acc;
    __syncthreads();
    if (s == 0) {
        float v = sh[c] + sh[c + 64] + sh[c + 128] + sh[c + 192];
        float cnt = (float)(hi - lo);
        out[g * HCD + c] = v / fmaxf(cnt, 1.f);
    }
}

// ---------------- launch -----------------------------------------------------
extern "C" void kernel_launch(void* const* d_in, const int* in_sizes, int n_in,
                              void* d_out, int out_size) {
    const float* x   = (const float*)d_in[0];
    const int*   ei  = (const int*)  d_in[1];
    const float* ea  = (const float*)d_in[2];
    const int*   bat = (const int*)  d_in[3];
    const float* W1  = (const float*)d_in[4];
    const float* We1 = (const float*)d_in[5];
    const float* as1 = (const float*)d_in[6];
    const float* ad1 = (const float*)d_in[7];
    const float* ae1 = (const float*)d_in[8];
    const float* b1  = (const float*)d_in[9];
    const float* W2  = (const float*)d_in[10];
    const float* We2 = (const float*)d_in[11];
    const float* as2 = (const float*)d_in[12];
    const float* ad2 = (const float*)d_in[13];
    const float* ae2 = (const float*)d_in[14];
    const float* b2  = (const float*)d_in[15];
    float* out = (float*)d_out;

    const int E8B = (NE / 8 + 255) / 256;          // 391 (8 edges/thread)
    const int FB  = (NN * 32 + 255) / 256;         // 6250 (one warp per node)
    const int LB  = (NN + 127) / 128;              // 391 linear tiles

    float *p_h1, *p_acc;
    int *p_deg;
    cudaGetSymbolAddress((void**)&p_h1,  g_h1);
    cudaGetSymbolAddress((void**)&p_acc, g_acc);
    cudaGetSymbolAddress((void**)&p_deg, g_deg);

    // Fork a side stream for the CSR build so it overlaps with k_linear<128>.
    cudaStream_t side = 0;
    cudaEvent_t evFork = 0, evJoin = 0;
    bool forked =
        (cudaStreamCreateWithFlags(&side, cudaStreamNonBlocking) == cudaSuccess) &&
        (cudaEventCreateWithFlags(&evFork, cudaEventDisableTiming) == cudaSuccess) &&
        (cudaEventCreateWithFlags(&evJoin, cudaEventDisableTiming) == cudaSuccess);

    cudaStream_t cs = forked ? side : 0;   // CSR stream

    if (forked) {
        cudaEventRecord(evFork, 0);            // fork point on capture stream
        cudaStreamWaitEvent(side, evFork, 0);
    }

    // ---- CSR build (side stream when forked) ----
    cudaMemsetAsync(p_deg, 0, NN * sizeof(int), cs);
    k_hist<<<E8B, 256, 0, cs>>>(ei, We1, ae1, We2, ae2);
    k_scanA<<<NTILES, 1024, 0, cs>>>();
    k_scanC<<<NTILES, 1024, 0, cs>>>();
    k_scatter<<<E8B, 256, 0, cs>>>(ei, ea);

    // ---- layer 1 linear (main stream, concurrent with CSR) ----
    k_linear<128><<<LB, 256>>>(x, W1, as1, ad1);

    if (forked) {
        cudaEventRecord(evJoin, side);         // join CSR chain back
        cudaStreamWaitEvent(0, evJoin, 0);
    }

    // ---- layer 1 aggregation ----
    k_edge_fused<<<FB, 256>>>(0, b1, p_h1, 1);

    // ---- layer 2 ----
    k_linear<64><<<LB, 256>>>(nullptr, W2, as2, ad2);
    k_edge_fused<<<FB, 256>>>(1, b2, p_acc, 0);

    // ---- pool ----
    k_pool<<<64, 256>>>(bat, out);
}

// round 16
// speedup vs baseline: 1.5434x; 1.5434x over previous
#include <cuda_runtime.h>

#define NN 50000
#define NE 800000
#define HCD 64
#define NTILES 49   // ceil(50000/1024)

// ---------------- scratch (static device globals; allocation-free) ----------
__device__ __align__(16) float g_xs[NN * HCD];      // xs of current layer
__device__ __align__(16) float g_h1[NN * HCD];      // relu(layer1 out)
__device__ __align__(16) float g_asrc[NN * 4];      // per-node a_src (4 heads)
__device__ __align__(16) float g_adst[NN * 4];      // per-node a_dst
__device__ __align__(16) float g_ce[8];             // [0..3] layer1, [4..7] layer2
__device__ float g_icnt[64];                        // 1/count per graph
// CSR build
__device__ int g_deg[NN];
__device__ int g_start[NN + 1];
__device__ int g_cursor[NN];
__device__ int g_bsum[NTILES];
__device__ __align__(16) int2 g_edge[NE];           // {src, ea bits} in CSR order

// ---------------- helpers ----------------------------------------------------
__device__ __forceinline__ float red16(float v) {
    v += __shfl_xor_sync(0xffffffffu, v, 8);
    v += __shfl_xor_sync(0xffffffffu, v, 4);
    v += __shfl_xor_sync(0xffffffffu, v, 2);
    v += __shfl_xor_sync(0xffffffffu, v, 1);
    return v;
}

__device__ __forceinline__ void red4(float* p, float a, float b, float c, float d) {
    asm volatile("red.global.add.v4.f32 [%0], {%1,%2,%3,%4};"
                 :: "l"(p), "f"(a), "f"(b), "f"(c), "f"(d) : "memory");
}

__device__ __forceinline__ int lowerb(const int* a, int n, int key) {
    int lo = 0, hi = n;
    while (lo < hi) { int m = (lo + hi) >> 1; if (a[m] < key) lo = m + 1; else hi = m; }
    return lo;
}

// ---------------- hist (8 edges/thread) + fused ce constants -----------------
__global__ void k_hist(const int* __restrict__ ei,
                       const float* __restrict__ We1, const float* __restrict__ ae1,
                       const float* __restrict__ We2, const float* __restrict__ ae2) {
    if (blockIdx.x == 0 && threadIdx.x < 128) {
        int t = threadIdx.x;
        int layer = t >> 6;
        int c = t & 63;
        const float* We = layer ? We2 : We1;
        const float* ae = layer ? ae2 : ae1;
        float v = red16(We[c] * ae[c]);
        if ((c & 15) == 0) g_ce[layer * 4 + (c >> 4)] = v;
    }
    int t = blockIdx.x * blockDim.x + threadIdx.x;
    int e = t * 8;
    if (e >= NE) return;
    int4 d0 = *(const int4*)&ei[NE + e];
    int4 d1 = *(const int4*)&ei[NE + e + 4];
    atomicAdd(&g_deg[d0.x], 1); atomicAdd(&g_deg[d0.y], 1);
    atomicAdd(&g_deg[d0.z], 1); atomicAdd(&g_deg[d0.w], 1);
    atomicAdd(&g_deg[d1.x], 1); atomicAdd(&g_deg[d1.y], 1);
    atomicAdd(&g_deg[d1.z], 1); atomicAdd(&g_deg[d1.w], 1);
}

// ---------------- per-graph inverse counts (batch is sorted) -----------------
__global__ void k_cnt(const int* __restrict__ batch) {
    int g = threadIdx.x;            // 64
    int lo = lowerb(batch, NN, g);
    int hi = lowerb(batch, NN, g + 1);
    g_icnt[g] = 1.f / fmaxf((float)(hi - lo), 1.f);
}

// ---------------- scan -------------------------------------------------------
__global__ void k_scanA() {           // per-tile reduction
    __shared__ int wsum[32];
    int b = blockIdx.x, tid = threadIdx.x, lane = tid & 31, w = tid >> 5;
    int i = b * 1024 + tid;
    int v = (i < NN) ? g_deg[i] : 0;
#pragma unroll
    for (int d = 16; d; d >>= 1) v += __shfl_xor_sync(0xffffffffu, v, d);
    if (lane == 0) wsum[w] = v;
    __syncthreads();
    if (w == 0) {
        int t = wsum[lane];
#pragma unroll
        for (int d = 16; d; d >>= 1) t += __shfl_xor_sync(0xffffffffu, t, d);
        if (lane == 0) g_bsum[b] = t;
    }
}

// per-tile scan + (redundant) scan of tile sums for the global offset.
// Cross-warp handoff uses BLOCK-level barriers.
__global__ void k_scanC() {
    __shared__ int wsum[32];
    __shared__ int sboff;
    __shared__ int ws2[2];
    int b = blockIdx.x, tid = threadIdx.x, lane = tid & 31, w = tid >> 5;

    int v2 = 0, x2 = 0;
    if (tid < 64) {
        v2 = (tid < NTILES) ? g_bsum[tid] : 0;
        x2 = v2;
#pragma unroll
        for (int d = 1; d < 32; d <<= 1) {
            int y = __shfl_up_sync(0xffffffffu, x2, d);
            if (lane >= d) x2 += y;
        }
        if (lane == 31) ws2[w] = x2;
    }
    __syncthreads();                       // publish ws2[0] to warp 1
    if (tid >= 32 && tid < 64) x2 += ws2[0];
    if (tid == b) sboff = x2 - v2;         // exclusive offset of this tile
    if (b == 0 && tid == NTILES - 1) g_start[NN] = x2;
    __syncthreads();                       // publish sboff

    int i = b * 1024 + tid;
    int v = (i < NN) ? g_deg[i] : 0;
    int x = v;
#pragma unroll
    for (int d = 1; d < 32; d <<= 1) {
        int y = __shfl_up_sync(0xffffffffu, x, d);
        if (lane >= d) x += y;
    }
    if (lane == 31) wsum[w] = x;
    __syncthreads();
    if (w == 0) {
        int t = wsum[lane];
#pragma unroll
        for (int d = 1; d < 32; d <<= 1) {
            int y = __shfl_up_sync(0xffffffffu, t, d);
            if (lane >= d) t += y;
        }
        wsum[lane] = t;
    }
    __syncthreads();
    int excl = sboff + (w ? wsum[w - 1] : 0) + x - v;
    if (i < NN) { g_start[i] = excl; g_cursor[i] = excl; }
}

// 8 edges per thread, vector loads for MLP.
__global__ void k_scatter(const int* __restrict__ ei, const float* __restrict__ ea) {
    int t = blockIdx.x * blockDim.x + threadIdx.x;
    int e = t * 8;
    if (e >= NE) return;
    int4   s0 = *(const int4*)&ei[e];
    int4   s1 = *(const int4*)&ei[e + 4];
    int4   d0 = *(const int4*)&ei[NE + e];
    int4   d1 = *(const int4*)&ei[NE + e + 4];
    float4 a0 = *(const float4*)&ea[e];
    float4 a1 = *(const float4*)&ea[e + 4];
    int p;
    p = atomicAdd(&g_cursor[d0.x], 1); g_edge[p] = make_int2(s0.x, __float_as_int(a0.x));
    p = atomicAdd(&g_cursor[d0.y], 1); g_edge[p] = make_int2(s0.y, __float_as_int(a0.y));
    p = atomicAdd(&g_cursor[d0.z], 1); g_edge[p] = make_int2(s0.z, __float_as_int(a0.z));
    p = atomicAdd(&g_cursor[d0.w], 1); g_edge[p] = make_int2(s0.w, __float_as_int(a0.w));
    p = atomicAdd(&g_cursor[d1.x], 1); g_edge[p] = make_int2(s1.x, __float_as_int(a1.x));
    p = atomicAdd(&g_cursor[d1.y], 1); g_edge[p] = make_int2(s1.y, __float_as_int(a1.y));
    p = atomicAdd(&g_cursor[d1.z], 1); g_edge[p] = make_int2(s1.z, __float_as_int(a1.z));
    p = atomicAdd(&g_cursor[d1.w], 1); g_edge[p] = make_int2(s1.w, __float_as_int(a1.w));
}

// ---------------- register-blocked linear ------------------------------------
template<int D>
__global__ void __launch_bounds__(256) k_linear(const float* __restrict__ Xext,
                                                const float* __restrict__ W,
                                                const float* __restrict__ as_,
                                                const float* __restrict__ ad_) {
    __shared__ float Wsh[D * 64];
    __shared__ float Xsh[128 * D];
    const float* X = Xext ? Xext : g_h1;
    int tid = threadIdx.x;
    int cg = tid & 7, ng = tid >> 3;
    int c0 = cg * 8;
    int h = cg >> 1;

    for (int i = tid * 4; i < D * 64; i += 1024)
        *(float4*)&Wsh[i] = *(const float4*)&W[i];

    int n0 = blockIdx.x * 128;
    int cnt = NN - n0; if (cnt > 128) cnt = 128;
    for (int i = tid * 4; i < cnt * D; i += 1024)
        *(float4*)&Xsh[i] = *(const float4*)&X[n0 * D + i];
    __syncthreads();

    float acc[4][8];
#pragma unroll
    for (int i = 0; i < 4; i++)
#pragma unroll
        for (int j = 0; j < 8; j++) acc[i][j] = 0.f;

#pragma unroll 2
    for (int k = 0; k < D; k++) {
        float4 wlo = *(const float4*)&Wsh[k * 64 + c0];
        float4 whi = *(const float4*)&Wsh[k * 64 + c0 + 4];
        float wr[8] = {wlo.x, wlo.y, wlo.z, wlo.w, whi.x, whi.y, whi.z, whi.w};
#pragma unroll
        for (int i = 0; i < 4; i++) {
            float xv = Xsh[(ng * 4 + i) * D + k];
#pragma unroll
            for (int j = 0; j < 8; j++)
                acc[i][j] = fmaf(xv, wr[j], acc[i][j]);
        }
    }

    float asv[8], adv[8];
#pragma unroll
    for (int j = 0; j < 8; j++) { asv[j] = as_[c0 + j]; adv[j] = ad_[c0 + j]; }

#pragma unroll
    for (int i = 0; i < 4; i++) {
        int node = n0 + ng * 4 + i;
        float ps = 0.f, pd = 0.f;
#pragma unroll
        for (int j = 0; j < 8; j++) {
            ps = fmaf(acc[i][j], asv[j], ps);
            pd = fmaf(acc[i][j], adv[j], pd);
        }
        ps += __shfl_xor_sync(0xffffffffu, ps, 1);
        pd += __shfl_xor_sync(0xffffffffu, pd, 1);
        if (node < NN) {
            float4 lo = make_float4(acc[i][0], acc[i][1], acc[i][2], acc[i][3]);
            float4 hi = make_float4(acc[i][4], acc[i][5], acc[i][6], acc[i][7]);
            *(float4*)&g_xs[node * HCD + c0] = lo;
            *(float4*)&g_xs[node * HCD + c0 + 4] = hi;
            if ((cg & 1) == 0) {
                g_asrc[node * 4 + h] = ps;
                g_adst[node * 4 + h] = pd;
            }
        }
    }
}

// ---------------- single-pass fused edge aggregation (one warp per dst) ------
// Unrolled x4: batch-load 4 edge records (2x int4), then 4 asrc + 4 xs gathers
// before any dependent math -> MLP ~8 outstanding loads per lane.
// Computes o0,o1 = the node's channels c, c+1 (bias applied by caller path).
__device__ __forceinline__ void edge_node(int layer, int gw, int lane,
                                          float& o0, float& o1) {
    int c = lane * 2;               // two consecutive channels, same head
    int h = lane >> 3;
    int s0 = g_start[gw], s1 = g_start[gw + 1];

    float adh = g_adst[gw * 4 + h];
    float cfh = g_ce[layer * 4 + h];

    float acc0 = 0.f, acc1 = 0.f, dsum = 0.f;

    int j = s0;
    // align j to even so int4 loads of g_edge are 16B-aligned
    if (j < s1 && (j & 1)) {
        int2 ep = g_edge[j];
        float sh = g_asrc[ep.x * 4 + h];
        float2 xv = *(const float2*)&g_xs[ep.x * HCD + c];
        float t = sh + adh + cfh * __int_as_float(ep.y);
        t = t > 0.f ? t : 0.2f * t;
        float w = __expf(t);
        dsum += w;
        acc0 = fmaf(w, xv.x, acc0);
        acc1 = fmaf(w, xv.y, acc1);
        ++j;
    }
    for (; j + 3 < s1; j += 4) {
        int4 eA = *(const int4*)&g_edge[j];
        int4 eB = *(const int4*)&g_edge[j + 2];
        int n0i = eA.x, n1i = eA.z, n2i = eB.x, n3i = eB.z;
        float sh0 = g_asrc[n0i * 4 + h];
        float sh1 = g_asrc[n1i * 4 + h];
        float sh2 = g_asrc[n2i * 4 + h];
        float sh3 = g_asrc[n3i * 4 + h];
        float2 x0 = *(const float2*)&g_xs[n0i * HCD + c];
        float2 x1 = *(const float2*)&g_xs[n1i * HCD + c];
        float2 x2 = *(const float2*)&g_xs[n2i * HCD + c];
        float2 x3 = *(const float2*)&g_xs[n3i * HCD + c];
        float t0 = sh0 + adh + cfh * __int_as_float(eA.y);
        float t1 = sh1 + adh + cfh * __int_as_float(eA.w);
        float t2 = sh2 + adh + cfh * __int_as_float(eB.y);
        float t3 = sh3 + adh + cfh * __int_as_float(eB.w);
        t0 = t0 > 0.f ? t0 : 0.2f * t0;
        t1 = t1 > 0.f ? t1 : 0.2f * t1;
        t2 = t2 > 0.f ? t2 : 0.2f * t2;
        t3 = t3 > 0.f ? t3 : 0.2f * t3;
        float w0 = __expf(t0), w1 = __expf(t1), w2 = __expf(t2), w3 = __expf(t3);
        dsum += (w0 + w1) + (w2 + w3);
        acc0 = fmaf(w0, x0.x, acc0); acc1 = fmaf(w0, x0.y, acc1);
        acc0 = fmaf(w1, x1.x, acc0); acc1 = fmaf(w1, x1.y, acc1);
        acc0 = fmaf(w2, x2.x, acc0); acc1 = fmaf(w2, x2.y, acc1);
        acc0 = fmaf(w3, x3.x, acc0); acc1 = fmaf(w3, x3.y, acc1);
    }
    for (; j < s1; ++j) {
        int2 ep = g_edge[j];
        float sh = g_asrc[ep.x * 4 + h];
        float2 xv = *(const float2*)&g_xs[ep.x * HCD + c];
        float t = sh + adh + cfh * __int_as_float(ep.y);
        t = t > 0.f ? t : 0.2f * t;
        float w = __expf(t);
        dsum += w;
        acc0 = fmaf(w, xv.x, acc0);
        acc1 = fmaf(w, xv.y, acc1);
    }

    float rcp = (dsum > 0.f) ? (1.f / dsum) : 0.f;
    o0 = acc0 * rcp;
    o1 = acc1 * rcp;
}

// layer-1: write h1 = relu(msg + b1)
__global__ void k_edge1(const float* __restrict__ bias) {
    int gw = (blockIdx.x * blockDim.x + threadIdx.x) >> 5;
    if (gw >= NN) return;
    int lane = threadIdx.x & 31;
    int c = lane * 2;
    float o0, o1;
    edge_node(0, gw, lane, o0, o1);
    float2 bv = *(const float2*)&bias[c];
    float2 ov;
    ov.x = fmaxf(o0 + bv.x, 0.f);
    ov.y = fmaxf(o1 + bv.y, 0.f);
    *(float2*)&g_h1[gw * HCD + c] = ov;
}

// layer-2 FUSED with mean-pool: red.add (msg + b2)/cnt[graph] into out.
__global__ void k_edge2_pool(const float* __restrict__ bias,
                             const int* __restrict__ batch,
                             float* __restrict__ out) {
    int gw = (blockIdx.x * blockDim.x + threadIdx.x) >> 5;
    if (gw >= NN) return;
    int lane = threadIdx.x & 31;
    int c = lane * 2;
    float o0, o1;
    edge_node(1, gw, lane, o0, o1);
    int g = batch[gw];                      // broadcast load
    float ic = g_icnt[g];
    float2 bv = *(const float2*)&bias[c];
    float v0 = (o0 + bv.x) * ic;
    float v1 = (o1 + bv.y) * ic;
    // pair lanes -> float4 red into out[g*64 + c] (16B aligned on even lanes)
    float v2 = __shfl_down_sync(0xffffffffu, v0, 1);
    float v3 = __shfl_down_sync(0xffffffffu, v1, 1);
    if ((lane & 1) == 0)
        red4(&out[g * HCD + c], v0, v1, v2, v3);
}

// ---------------- launch -----------------------------------------------------
extern "C" void kernel_launch(void* const* d_in, const int* in_sizes, int n_in,
                              void* d_out, int out_size) {
    const float* x   = (const float*)d_in[0];
    const int*   ei  = (const int*)  d_in[1];
    const float* ea  = (const float*)d_in[2];
    const int*   bat = (const int*)  d_in[3];
    const float* W1  = (const float*)d_in[4];
    const float* We1 = (const float*)d_in[5];
    const float* as1 = (const float*)d_in[6];
    const float* ad1 = (const float*)d_in[7];
    const float* ae1 = (const float*)d_in[8];
    const float* b1  = (const float*)d_in[9];
    const float* W2  = (const float*)d_in[10];
    const float* We2 = (const float*)d_in[11];
    const float* as2 = (const float*)d_in[12];
    const float* ad2 = (const float*)d_in[13];
    const float* ae2 = (const float*)d_in[14];
    const float* b2  = (const float*)d_in[15];
    float* out = (float*)d_out;

    const int E8B = (NE / 8 + 255) / 256;          // 391 (8 edges/thread)
    const int FB  = (NN * 32 + 255) / 256;         // 6250 (one warp per node)
    const int LB  = (NN + 127) / 128;              // 391 linear tiles

    int *p_deg;
    cudaGetSymbolAddress((void**)&p_deg, g_deg);

    // Fork a side stream for the CSR build so it overlaps with k_linear<128>.
    cudaStream_t side = 0;
    cudaEvent_t evFork = 0, evJoin = 0;
    bool forked =
        (cudaStreamCreateWithFlags(&side, cudaStreamNonBlocking) == cudaSuccess) &&
        (cudaEventCreateWithFlags(&evFork, cudaEventDisableTiming) == cudaSuccess) &&
        (cudaEventCreateWithFlags(&evJoin, cudaEventDisableTiming) == cudaSuccess);

    cudaStream_t cs = forked ? side : 0;   // CSR stream

    if (forked) {
        cudaEventRecord(evFork, 0);            // fork point on capture stream
        cudaStreamWaitEvent(side, evFork, 0);
    }

    // ---- CSR build + pool prep (side stream when forked) ----
    cudaMemsetAsync(p_deg, 0, NN * sizeof(int), cs);
    cudaMemsetAsync(out, 0, 64 * HCD * sizeof(float), cs);
    k_cnt<<<1, 64, 0, cs>>>(bat);
    k_hist<<<E8B, 256, 0, cs>>>(ei, We1, ae1, We2, ae2);
    k_scanA<<<NTILES, 1024, 0, cs>>>();
    k_scanC<<<NTILES, 1024, 0, cs>>>();
    k_scatter<<<E8B, 256, 0, cs>>>(ei, ea);

    // ---- layer 1 linear (main stream, concurrent with CSR) ----
    k_linear<128><<<LB, 256>>>(x, W1, as1, ad1);

    if (forked) {
        cudaEventRecord(evJoin, side);         // join CSR chain back
        cudaStreamWaitEvent(0, evJoin, 0);
    }

    // ---- layer 1 aggregation ----
    k_edge1<<<FB, 256>>>(b1);

    // ---- layer 2 linear ----
    k_linear<64><<<LB, 256>>>(nullptr, W2, as2, ad2);

    // ---- layer 2 aggregation fused with mean pool ----
    k_edge2_pool<<<FB, 256>>>(b2, bat, out);
}